// round 4
// baseline (speedup 1.0000x reference)
#include <cuda_runtime.h>
#include <math.h>

#define Bsz 2
#define Ssz 2048
#define Dsz 1024
#define Hn  16
#define DHs 64
#define Mrows (Bsz*Ssz)

// Scratch (static device globals; no runtime allocation)
__device__ float g_xq[Mrows*Dsz];   // inputs, tf32 + pi32-permuted cols
__device__ float g_xk[Mrows*Dsz];
__device__ float g_xv[Mrows*Dsz];
__device__ float g_wq[Dsz*Dsz];     // weights, tf32 + pi64-permuted cols
__device__ float g_wk[Dsz*Dsz];
__device__ float g_wv[Dsz*Dsz];
__device__ float g_wo[Dsz*Dsz];
__device__ float g_q[Mrows*Dsz];    // [B,H,S,64] tf32 (Q,K: plain dh; V: pi64 dh)
__device__ float g_k[Mrows*Dsz];
__device__ float g_v[Mrows*Dsz];
__device__ float g_o[Mrows*Dsz];    // [M,1024] tf32 + pi32-permuted cols

// ---------------------------------------------------------------------------
// helpers
// ---------------------------------------------------------------------------
__device__ __forceinline__ unsigned f2tf32(float x) {
    unsigned r;
    asm("cvt.rna.tf32.f32 %0, %1;" : "=r"(r) : "f"(x));
    return r;
}
__device__ __forceinline__ float tf32f(float x) { return __uint_as_float(f2tf32(x)); }

__device__ __forceinline__ float ex2(float x) {
    float r; asm("ex2.approx.ftz.f32 %0, %1;" : "=f"(r) : "f"(x)); return r;
}

__device__ __forceinline__ void mma_tf32(float* c, const unsigned* a, const unsigned* b) {
    asm volatile(
        "mma.sync.aligned.m16n8k8.row.col.f32.tf32.tf32.f32 "
        "{%0,%1,%2,%3}, {%4,%5,%6,%7}, {%8,%9}, {%0,%1,%2,%3};"
        : "+f"(c[0]), "+f"(c[1]), "+f"(c[2]), "+f"(c[3])
        : "r"(a[0]), "r"(a[1]), "r"(a[2]), "r"(a[3]), "r"(b[0]), "r"(b[1]));
}

__device__ __forceinline__ void cp_async16(void* smem, const void* gmem) {
    unsigned s = (unsigned)__cvta_generic_to_shared(smem);
    asm volatile("cp.async.cg.shared.global [%0], [%1], 16;" :: "r"(s), "l"(gmem));
}
#define CP_COMMIT() asm volatile("cp.async.commit_group;")
#define CP_WAIT1()  asm volatile("cp.async.wait_group 1;")
#define CP_WAIT0()  asm volatile("cp.async.wait_group 0;")

// ---------------------------------------------------------------------------
// convert+permute kernels
// pi32(x) = ((x&7)<<2)|(x>>3) within 32-wide windows (GEMM A fragments)
// pi64(x) = ((x&7)<<3)|(x>>3) within 64-wide windows (GEMM B fragments)
// ---------------------------------------------------------------------------
__global__ void cvt_x(const float* __restrict__ in, float* __restrict__ out) {
    size_t base = ((size_t)blockIdx.x * 256 + threadIdx.x) * 4;
    float4 v = *(const float4*)&in[base];
    unsigned low = (unsigned)(base & 31);
    size_t p = (base & ~(size_t)31) + (((low & 7) << 2) | (low >> 3));
    out[p]      = tf32f(v.x);
    out[p + 4]  = tf32f(v.y);
    out[p + 8]  = tf32f(v.z);
    out[p + 12] = tf32f(v.w);
}
__global__ void cvt_w(const float* __restrict__ in, float* __restrict__ out) {
    size_t base = ((size_t)blockIdx.x * 256 + threadIdx.x) * 4;
    float4 v = *(const float4*)&in[base];
    unsigned low = (unsigned)(base & 63);
    size_t p = (base & ~(size_t)63) + (((low & 7) << 3) | (low >> 3));
    out[p]      = tf32f(v.x);
    out[p + 8]  = tf32f(v.y);
    out[p + 16] = tf32f(v.z);
    out[p + 24] = tf32f(v.w);
}

// ---------------------------------------------------------------------------
// TF32 GEMM on pre-converted/pre-permuted operands.
// 128x128 tile, BK=32, 256 threads (8 warps 4Mx2N), cp.async 2-stage.
// MODE 0: final, fp32, plain [M,1024] float2 stores
// MODE 1: Q/K projection: head-split [B,H,S,64], tf32, plain dh
// MODE 2: V projection: head-split, tf32, dh permuted by pi64
// ---------------------------------------------------------------------------
#define A_PITCH 36
#define B_PITCH 132
#define GEMM_SMEM ((2*128*A_PITCH + 2*32*B_PITCH) * 4)

template<int MODE>
__global__ __launch_bounds__(256, 2)
void gemm_tf32(const float* __restrict__ X, const float* __restrict__ W,
               const float* __restrict__ bias, float* __restrict__ out,
               float scale)
{
    extern __shared__ float sm[];
    float* As = sm;                       // [2][128][36]
    float* Bs = sm + 2*128*A_PITCH;       // [2][32][132]

    const int tid  = threadIdx.x;
    const int lane = tid & 31;
    const int warp = tid >> 5;
    const int g  = lane >> 2;
    const int tg = lane & 3;
    const int m0w = (warp >> 1) * 32;
    const int n0w = (warp & 1) * 64;
    const int row0 = blockIdx.y * 128;
    const int col0 = blockIdx.x * 128;

    float c[2][8][4] = {};

    auto load_stage = [&](int kt, int p) {
        float* Ad = As + p*128*A_PITCH;
        float* Bd = Bs + p*32*B_PITCH;
        #pragma unroll
        for (int i = 0; i < 4; i++) {
            int idx = tid + i*256;
            int r = idx >> 3, c4 = idx & 7;
            cp_async16(&Ad[r*A_PITCH + c4*4], &X[(size_t)(row0 + r)*Dsz + kt*32 + c4*4]);
        }
        #pragma unroll
        for (int i = 0; i < 4; i++) {
            int idx = tid + i*256;
            int r = idx >> 5, c4 = idx & 31;
            cp_async16(&Bd[r*B_PITCH + c4*4], &W[(size_t)(kt*32 + r)*Dsz + col0 + c4*4]);
        }
    };

    load_stage(0, 0);
    CP_COMMIT();

    const int NT = Dsz / 32;
    for (int kt = 0; kt < NT; kt++) {
        int p = kt & 1;
        if (kt + 1 < NT) {
            load_stage(kt + 1, p ^ 1);
            CP_COMMIT();
            CP_WAIT1();
        } else {
            CP_WAIT0();
        }
        __syncthreads();

        const float* Ap = As + p*128*A_PITCH;
        const float* Bp = Bs + p*32*B_PITCH;

        float a4[2][4][4];
        #pragma unroll
        for (int mi = 0; mi < 2; mi++) {
            int r = m0w + mi*16 + g;
            *(float4*)a4[mi][0] = *(const float4*)&Ap[r*A_PITCH + tg*4];
            *(float4*)a4[mi][1] = *(const float4*)&Ap[(r+8)*A_PITCH + tg*4];
            *(float4*)a4[mi][2] = *(const float4*)&Ap[r*A_PITCH + (tg+4)*4];
            *(float4*)a4[mi][3] = *(const float4*)&Ap[(r+8)*A_PITCH + (tg+4)*4];
        }
        #pragma unroll
        for (int ks = 0; ks < 4; ks++) {
            float b0[8], b1[8];
            const float* Br0 = &Bp[(ks*8 + tg)*B_PITCH + n0w + g*8];
            const float* Br1 = &Bp[(ks*8 + tg + 4)*B_PITCH + n0w + g*8];
            *(float4*)&b0[0] = *(const float4*)&Br0[0];
            *(float4*)&b0[4] = *(const float4*)&Br0[4];
            *(float4*)&b1[0] = *(const float4*)&Br1[0];
            *(float4*)&b1[4] = *(const float4*)&Br1[4];

            unsigned a[2][4];
            #pragma unroll
            for (int mi = 0; mi < 2; mi++)
                #pragma unroll
                for (int pp = 0; pp < 4; pp++)
                    a[mi][pp] = __float_as_uint(a4[mi][pp][ks]);

            #pragma unroll
            for (int mi = 0; mi < 2; mi++)
                #pragma unroll
                for (int ni = 0; ni < 8; ni++) {
                    unsigned bf[2] = { __float_as_uint(b0[ni]), __float_as_uint(b1[ni]) };
                    mma_tf32(c[mi][ni], a[mi], bf);
                }
        }
        __syncthreads();
    }

    #pragma unroll
    for (int mi = 0; mi < 2; mi++) {
        #pragma unroll
        for (int ni = 0; ni < 8; ni++) {
            int cc = col0 + n0w + ni*8 + 2*tg;
            float bx = bias[cc], by = bias[cc+1];
            #pragma unroll
            for (int rr = 0; rr < 2; rr++) {
                int r = row0 + m0w + mi*16 + g + rr*8;
                float vx = (c[mi][ni][rr*2+0] + bx) * scale;
                float vy = (c[mi][ni][rr*2+1] + by) * scale;
                if (MODE == 0) {
                    float2 v = make_float2(vx, vy);
                    *(float2*)&out[(size_t)r * Dsz + cc] = v;
                } else {
                    int b_ = r >> 11, s_ = r & (Ssz-1);
                    int h_ = cc >> 6, dh = cc & (DHs-1);
                    size_t base = (((size_t)(b_*Hn + h_) * Ssz) + s_) * DHs;
                    if (MODE == 1) {
                        float2 v = make_float2(tf32f(vx), tf32f(vy));
                        *(float2*)&out[base + dh] = v;
                    } else {  // MODE 2: V, dh -> pi64(dh)
                        int p0 = ((dh & 7) << 3) | (dh >> 3);
                        out[base + p0]     = tf32f(vx);
                        out[base + p0 + 8] = tf32f(vy);
                    }
                }
            }
        }
    }
}

// ---------------------------------------------------------------------------
// Flash attention, tf32 MMA, vectorized fragments.
// Q fragments registers-resident (relabel: mma-k ks*8+tg <-> actual d tg*8+ks).
// Kt stores row = pi64(d), col = pi64(kv); S-loop reads row (ks*8+tg), which
// holds actual d = tg*8+ks -- matching Q's relabel.  [R3 bug: read tg*8+ks]
// Vs rows = actual kv (plain cp.async; V gmem cols pre-permuted pi64(dh)).
// ---------------------------------------------------------------------------
#define P68 68
#define KV_T 17408                      // 64*68*4 bytes per stage
#define ATTN_SMEM (2*KV_T + 3*KV_T + 128*P68*4)

__global__ __launch_bounds__(256, 1)
void attn_mma(const float* __restrict__ Q, const float* __restrict__ K,
              const float* __restrict__ V, float* __restrict__ O)
{
    extern __shared__ float sm[];
    float* Kt = sm;                      // [2][64][68]
    float* Vs = sm + 2*64*P68;           // [3][64][68]
    float* Ps = sm + 5*64*P68;           // [128][68]

    const int tid  = threadIdx.x;
    const int lane = tid & 31;
    const int warp = tid >> 5;
    const int g  = lane >> 2;
    const int tg = lane & 3;
    const int m0w = warp * 16;
    const int r0 = m0w + g;

    const int q0 = blockIdx.x * 128;
    const int h = blockIdx.y, b = blockIdx.z;
    const size_t base = ((size_t)(b*Hn + h)) * Ssz * DHs;
    const float* Qg = Q + base;
    const float* Kg = K + base;
    const float* Vg = V + base;

    // ---- Q fragments: 8 LDG.128, registers for all tiles ----
    float aqf[4][8];
    {
        const float* Qr0 = &Qg[(size_t)(q0 + r0) * DHs];
        const float* Qr1 = &Qg[(size_t)(q0 + r0 + 8) * DHs];
        *(float4*)&aqf[0][0] = *(const float4*)&Qr0[tg*8];
        *(float4*)&aqf[0][4] = *(const float4*)&Qr0[tg*8 + 4];
        *(float4*)&aqf[1][0] = *(const float4*)&Qr1[tg*8];
        *(float4*)&aqf[1][4] = *(const float4*)&Qr1[tg*8 + 4];
        *(float4*)&aqf[2][0] = *(const float4*)&Qr0[(tg+4)*8];
        *(float4*)&aqf[2][4] = *(const float4*)&Qr0[(tg+4)*8 + 4];
        *(float4*)&aqf[3][0] = *(const float4*)&Qr1[(tg+4)*8];
        *(float4*)&aqf[3][4] = *(const float4*)&Qr1[(tg+4)*8 + 4];
    }

    float kreg[4][4];   // K prefetch registers

    auto ldg_K = [&](int t0) {
        #pragma unroll
        for (int i = 0; i < 4; i++) {
            int idx = tid + i*256;
            int r = idx >> 4, c4 = idx & 15;
            *(float4*)kreg[i] = *(const float4*)&Kg[(size_t)(t0 + r) * DHs + c4*4];
        }
    };
    auto sts_K = [&](float* dst) {
        #pragma unroll
        for (int i = 0; i < 4; i++) {
            int idx = tid + i*256;
            int r = idx >> 4, c4 = idx & 15;
            int pcol = ((r & 7) << 3) | (r >> 3);          // pi64(kv)
            int dbase = ((c4 & 1) << 5);
            int dlow  = c4 >> 1;
            #pragma unroll
            for (int j = 0; j < 4; j++)
                dst[(dbase + j*8 + dlow)*P68 + pcol] = kreg[i][j];   // row = pi64(d)
        }
    };
    auto cpa_V = [&](int t0, float* dst) {
        #pragma unroll
        for (int i = 0; i < 4; i++) {
            int idx = tid + i*256;
            int r = idx >> 4, c4 = idx & 15;
            cp_async16(&dst[r*P68 + c4*4], &Vg[(size_t)(t0 + r) * DHs + c4*4]);
        }
    };

    // ---- prologue ----
    cpa_V(0, Vs);             CP_COMMIT();
    ldg_K(0);  sts_K(Kt);
    cpa_V(64, Vs + 64*P68);   CP_COMMIT();
    ldg_K(64);
    CP_WAIT1();
    __syncthreads();

    float o[8][4] = {};
    float m0 = -1e30f, m1 = -1e30f, l0 = 0.0f, l1 = 0.0f;

    const int NTILE = Ssz / 64;   // 32
    for (int t = 0; t < NTILE; t++) {
        const int kp = t & 1;
        const float* Ktp = Kt + kp*64*P68;
        const float* Vsp = Vs + (t % 3)*64*P68;

        // ---- S = Q @ K^T ----
        float s[8][4] = {};
        #pragma unroll
        for (int ks = 0; ks < 8; ks++) {
            float b0[8], b1[8];
            // FIX (R3 bug): row ks*8+tg holds actual d = tg*8+ks (pi64 involution),
            // matching Q's relabel. R3 read row tg*8+ks -> mismatched d pairing.
            const float* Kr0 = &Ktp[(ks*8 + tg)*P68 + g*8];
            const float* Kr1 = &Ktp[(ks*8 + tg + 4)*P68 + g*8];
            *(float4*)&b0[0] = *(const float4*)&Kr0[0];
            *(float4*)&b0[4] = *(const float4*)&Kr0[4];
            *(float4*)&b1[0] = *(const float4*)&Kr1[0];
            *(float4*)&b1[4] = *(const float4*)&Kr1[4];
            unsigned a[4] = { __float_as_uint(aqf[0][ks]), __float_as_uint(aqf[1][ks]),
                              __float_as_uint(aqf[2][ks]), __float_as_uint(aqf[3][ks]) };
            #pragma unroll
            for (int nt = 0; nt < 8; nt++) {
                unsigned bf[2] = { __float_as_uint(b0[nt]), __float_as_uint(b1[nt]) };
                mma_tf32(s[nt], a, bf);
            }
        }

        // K_{t+1} -> smem (other stage; visibility via end-of-iter sync)
        if (t + 1 < NTILE) sts_K(Kt + (kp^1)*64*P68);

        // ---- online softmax (base-2; Q pre-scaled by log2e/8) ----
        float rm0 = -1e30f, rm1 = -1e30f;
        #pragma unroll
        for (int nt = 0; nt < 8; nt++) {
            rm0 = fmaxf(rm0, fmaxf(s[nt][0], s[nt][1]));
            rm1 = fmaxf(rm1, fmaxf(s[nt][2], s[nt][3]));
        }
        rm0 = fmaxf(rm0, __shfl_xor_sync(0xffffffffu, rm0, 1));
        rm0 = fmaxf(rm0, __shfl_xor_sync(0xffffffffu, rm0, 2));
        rm1 = fmaxf(rm1, __shfl_xor_sync(0xffffffffu, rm1, 1));
        rm1 = fmaxf(rm1, __shfl_xor_sync(0xffffffffu, rm1, 2));

        float mn0 = fmaxf(m0, rm0), mn1 = fmaxf(m1, rm1);
        float al0 = ex2(m0 - mn0), al1 = ex2(m1 - mn1);
        m0 = mn0; m1 = mn1;

        float rs0 = 0.0f, rs1 = 0.0f;
        #pragma unroll
        for (int nt = 0; nt < 8; nt++) {
            s[nt][0] = ex2(s[nt][0] - m0);
            s[nt][1] = ex2(s[nt][1] - m0);
            s[nt][2] = ex2(s[nt][2] - m1);
            s[nt][3] = ex2(s[nt][3] - m1);
            rs0 += s[nt][0] + s[nt][1];
            rs1 += s[nt][2] + s[nt][3];
        }
        rs0 += __shfl_xor_sync(0xffffffffu, rs0, 1);
        rs0 += __shfl_xor_sync(0xffffffffu, rs0, 2);
        rs1 += __shfl_xor_sync(0xffffffffu, rs1, 1);
        rs1 += __shfl_xor_sync(0xffffffffu, rs1, 2);

        l0 = l0 * al0 + rs0;
        l1 = l1 * al1 + rs1;
        #pragma unroll
        for (int nt = 0; nt < 8; nt++) {
            o[nt][0] *= al0; o[nt][1] *= al0;
            o[nt][2] *= al1; o[nt][3] *= al1;
        }

        // ---- P -> smem (warp-local rows), tf32-cvt'd ----
        __syncwarp();
        #pragma unroll
        for (int nt = 0; nt < 8; nt++) {
            float2 p01 = make_float2(tf32f(s[nt][0]), tf32f(s[nt][1]));
            float2 p23 = make_float2(tf32f(s[nt][2]), tf32f(s[nt][3]));
            *(float2*)&Ps[r0*P68 + nt*8 + 2*tg]       = p01;
            *(float2*)&Ps[(r0+8)*P68 + nt*8 + 2*tg]   = p23;
        }
        __syncwarp();

        // ---- O += P @ V ----
        float pa[4][8];
        {
            const float* Pr0 = &Ps[r0*P68];
            const float* Pr1 = &Ps[(r0+8)*P68];
            *(float4*)&pa[0][0] = *(const float4*)&Pr0[tg*8];
            *(float4*)&pa[0][4] = *(const float4*)&Pr0[tg*8 + 4];
            *(float4*)&pa[1][0] = *(const float4*)&Pr1[tg*8];
            *(float4*)&pa[1][4] = *(const float4*)&Pr1[tg*8 + 4];
            *(float4*)&pa[2][0] = *(const float4*)&Pr0[(tg+4)*8];
            *(float4*)&pa[2][4] = *(const float4*)&Pr0[(tg+4)*8 + 4];
            *(float4*)&pa[3][0] = *(const float4*)&Pr1[(tg+4)*8];
            *(float4*)&pa[3][4] = *(const float4*)&Pr1[(tg+4)*8 + 4];
        }
        #pragma unroll
        for (int ks = 0; ks < 8; ks++) {
            float b0[8], b1[8];
            // Vs rows = actual kv; P relabel kv = tg_eff*8+ks -> read row tg_eff*8+ks
            const float* Vr0 = &Vsp[(tg*8 + ks)*P68 + g*8];
            const float* Vr1 = &Vsp[((tg+4)*8 + ks)*P68 + g*8];
            *(float4*)&b0[0] = *(const float4*)&Vr0[0];
            *(float4*)&b0[4] = *(const float4*)&Vr0[4];
            *(float4*)&b1[0] = *(const float4*)&Vr1[0];
            *(float4*)&b1[4] = *(const float4*)&Vr1[4];
            unsigned a[4] = { __float_as_uint(pa[0][ks]), __float_as_uint(pa[1][ks]),
                              __float_as_uint(pa[2][ks]), __float_as_uint(pa[3][ks]) };
            #pragma unroll
            for (int nt = 0; nt < 8; nt++) {
                unsigned bf[2] = { __float_as_uint(b0[nt]), __float_as_uint(b1[nt]) };
                mma_tf32(o[nt], a, bf);
            }
        }

        // ---- prefetch tile t+2 ----
        if (t + 2 < NTILE) {
            cpa_V((t+2)*64, Vs + ((t+2) % 3)*64*P68);
            CP_COMMIT();
            ldg_K((t+2)*64);
        }
        if (t + 2 < NTILE) { CP_WAIT1(); } else { CP_WAIT0(); }
        __syncthreads();
    }

    // ---- normalize + write O: tf32, pi32-permuted cols (feeds final GEMM) ----
    float inv0 = 1.0f / l0, inv1 = 1.0f / l1;
    size_t ob0 = ((size_t)(b*Ssz + q0 + r0)) * Dsz;
    size_t ob1 = ((size_t)(b*Ssz + q0 + r0 + 8)) * Dsz;
    #pragma unroll
    for (int nt = 0; nt < 8; nt++) {
        #pragma unroll
        for (int j = 0; j < 2; j++) {
            int n = nt*8 + 2*tg + j;
            int c = h*DHs + n;
            int pos = (c & ~31) | (((c & 7) << 2) | ((c & 31) >> 3));
            O[ob0 + pos] = tf32f(o[nt][j]   * inv0);
            O[ob1 + pos] = tf32f(o[nt][2+j] * inv1);
        }
    }
}

// ---------------------------------------------------------------------------

extern "C" void kernel_launch(void* const* d_in, const int* in_sizes, int n_in,
                              void* d_out, int out_size)
{
    (void)in_sizes; (void)n_in; (void)out_size;
    const float* queries = (const float*)d_in[0];
    const float* keys    = (const float*)d_in[1];
    const float* values  = (const float*)d_in[2];
    const float* Wq = (const float*)d_in[3];
    const float* bq = (const float*)d_in[4];
    const float* Wk = (const float*)d_in[5];
    const float* bk = (const float*)d_in[6];
    const float* Wv = (const float*)d_in[7];
    const float* bv = (const float*)d_in[8];
    const float* Wo = (const float*)d_in[9];
    const float* bo = (const float*)d_in[10];
    float* out = (float*)d_out;

    void *pxq,*pxk,*pxv,*pwq,*pwk,*pwv,*pwo,*pq,*pk,*pv,*po;
    cudaGetSymbolAddress(&pxq, g_xq); cudaGetSymbolAddress(&pxk, g_xk);
    cudaGetSymbolAddress(&pxv, g_xv);
    cudaGetSymbolAddress(&pwq, g_wq); cudaGetSymbolAddress(&pwk, g_wk);
    cudaGetSymbolAddress(&pwv, g_wv); cudaGetSymbolAddress(&pwo, g_wo);
    cudaGetSymbolAddress(&pq, g_q);   cudaGetSymbolAddress(&pk, g_k);
    cudaGetSymbolAddress(&pv, g_v);   cudaGetSymbolAddress(&po, g_o);

    cudaFuncSetAttribute(gemm_tf32<0>, cudaFuncAttributeMaxDynamicSharedMemorySize, GEMM_SMEM);
    cudaFuncSetAttribute(gemm_tf32<1>, cudaFuncAttributeMaxDynamicSharedMemorySize, GEMM_SMEM);
    cudaFuncSetAttribute(gemm_tf32<2>, cudaFuncAttributeMaxDynamicSharedMemorySize, GEMM_SMEM);
    cudaFuncSetAttribute(attn_mma,     cudaFuncAttributeMaxDynamicSharedMemorySize, ATTN_SMEM);

    // convert + permute (tf32)
    cvt_x<<<Mrows*Dsz/1024, 256>>>(queries, (float*)pxq);
    cvt_x<<<Mrows*Dsz/1024, 256>>>(keys,    (float*)pxk);
    cvt_x<<<Mrows*Dsz/1024, 256>>>(values,  (float*)pxv);
    cvt_w<<<Dsz*Dsz/1024, 256>>>(Wq, (float*)pwq);
    cvt_w<<<Dsz*Dsz/1024, 256>>>(Wk, (float*)pwk);
    cvt_w<<<Dsz*Dsz/1024, 256>>>(Wv, (float*)pwv);
    cvt_w<<<Dsz*Dsz/1024, 256>>>(Wo, (float*)pwo);

    dim3 ggrid(Dsz/128, Mrows/128);   // (8, 32)
    const float qscale = 0.125f * 1.4426950408889634f;   // log2e / sqrt(64)

    gemm_tf32<1><<<ggrid, 256, GEMM_SMEM>>>((const float*)pxq, (const float*)pwq, bq, (float*)pq, qscale);
    gemm_tf32<1><<<ggrid, 256, GEMM_SMEM>>>((const float*)pxk, (const float*)pwk, bk, (float*)pk, 1.0f);
    gemm_tf32<2><<<ggrid, 256, GEMM_SMEM>>>((const float*)pxv, (const float*)pwv, bv, (float*)pv, 1.0f);

    dim3 agrid(Ssz/128, Hn, Bsz);     // (16, 16, 2)
    attn_mma<<<agrid, 256, ATTN_SMEM>>>((const float*)pq, (const float*)pk,
                                        (const float*)pv, (float*)po);

    gemm_tf32<0><<<ggrid, 256, GEMM_SMEM>>>((const float*)po, (const float*)pwo, bo, out, 1.0f);
}

// round 5
// speedup vs baseline: 1.1449x; 1.1449x over previous
#include <cuda_runtime.h>
#include <math.h>

#define Bsz 2
#define Ssz 2048
#define Dsz 1024
#define Hn  16
#define DHs 64
#define Mrows (Bsz*Ssz)

// Scratch (static device globals; no runtime allocation)
__device__ float g_q[Mrows*Dsz];    // [B,H,S,64] tf32-rounded (Q,K: plain dh; V: pi64 dh)
__device__ float g_k[Mrows*Dsz];
__device__ float g_v[Mrows*Dsz];
__device__ float g_o[Mrows*Dsz];    // [M,1024] fp32 plain

// ---------------------------------------------------------------------------
// helpers
// ---------------------------------------------------------------------------
__device__ __forceinline__ unsigned f2tf32(float x) {
    unsigned r;
    asm("cvt.rna.tf32.f32 %0, %1;" : "=r"(r) : "f"(x));
    return r;
}
__device__ __forceinline__ float tf32f(float x) { return __uint_as_float(f2tf32(x)); }

__device__ __forceinline__ float ex2(float x) {
    float r; asm("ex2.approx.ftz.f32 %0, %1;" : "=f"(r) : "f"(x)); return r;
}

__device__ __forceinline__ void mma_tf32(float* c, const unsigned* a, const unsigned* b) {
    asm volatile(
        "mma.sync.aligned.m16n8k8.row.col.f32.tf32.tf32.f32 "
        "{%0,%1,%2,%3}, {%4,%5,%6,%7}, {%8,%9}, {%0,%1,%2,%3};"
        : "+f"(c[0]), "+f"(c[1]), "+f"(c[2]), "+f"(c[3])
        : "r"(a[0]), "r"(a[1]), "r"(a[2]), "r"(a[3]), "r"(b[0]), "r"(b[1]));
}

__device__ __forceinline__ void cp_async16(void* smem, const void* gmem) {
    unsigned s = (unsigned)__cvta_generic_to_shared(smem);
    asm volatile("cp.async.cg.shared.global [%0], [%1], 16;" :: "r"(s), "l"(gmem));
}
#define CP_COMMIT() asm volatile("cp.async.commit_group;")
#define CP_WAIT1()  asm volatile("cp.async.wait_group 1;")
#define CP_WAIT0()  asm volatile("cp.async.wait_group 0;")

// ---------------------------------------------------------------------------
// TF32 GEMM — EXACT R2 main loop (measured-good). Epilogue modes:
// MODE 0: plain [M,1024] fp32 float2 stores (final projection output)
// MODE 1: Q/K: head-split [B,H,S,64], tf32-rounded, plain dh
// MODE 2: V:   head-split, tf32-rounded, dh -> pi64(dh) = ((dh&7)<<3)|(dh>>3)
// ---------------------------------------------------------------------------
#define A_PITCH 36
#define B_PITCH 132
#define GEMM_SMEM ((2*128*A_PITCH + 2*32*B_PITCH) * 4)

template<int MODE>
__global__ __launch_bounds__(256, 2)
void gemm_tf32(const float* __restrict__ X, const float* __restrict__ W,
               const float* __restrict__ bias, float* __restrict__ out,
               float scale)
{
    extern __shared__ float sm[];
    float* As = sm;                       // [2][128][36]
    float* Bs = sm + 2*128*A_PITCH;       // [2][32][132]

    const int tid  = threadIdx.x;
    const int lane = tid & 31;
    const int warp = tid >> 5;
    const int g  = lane >> 2;
    const int tg = lane & 3;
    const int m0w = (warp >> 1) * 32;
    const int n0w = (warp & 1) * 64;
    const int row0 = blockIdx.y * 128;
    const int col0 = blockIdx.x * 128;

    float c[2][8][4] = {};

    auto load_stage = [&](int kt, int p) {
        float* Ad = As + p*128*A_PITCH;
        float* Bd = Bs + p*32*B_PITCH;
        #pragma unroll
        for (int i = 0; i < 4; i++) {
            int idx = tid + i*256;
            int r = idx >> 3, c4 = idx & 7;
            cp_async16(&Ad[r*A_PITCH + c4*4], &X[(size_t)(row0 + r)*Dsz + kt*32 + c4*4]);
        }
        #pragma unroll
        for (int i = 0; i < 4; i++) {
            int idx = tid + i*256;
            int r = idx >> 5, c4 = idx & 31;
            cp_async16(&Bd[r*B_PITCH + c4*4], &W[(size_t)(kt*32 + r)*Dsz + col0 + c4*4]);
        }
    };

    load_stage(0, 0);
    CP_COMMIT();

    const int NT = Dsz / 32;
    for (int kt = 0; kt < NT; kt++) {
        int p = kt & 1;
        if (kt + 1 < NT) {
            load_stage(kt + 1, p ^ 1);
            CP_COMMIT();
            CP_WAIT1();
        } else {
            CP_WAIT0();
        }
        __syncthreads();

        const float* Ap = As + p*128*A_PITCH;
        const float* Bp = Bs + p*32*B_PITCH;
        #pragma unroll
        for (int ks = 0; ks < 4; ks++) {
            unsigned a[2][4], b[8][2];
            #pragma unroll
            for (int mi = 0; mi < 2; mi++) {
                int r = m0w + mi*16 + g;
                int kc = ks*8 + tg;
                a[mi][0] = f2tf32(Ap[r*A_PITCH + kc]);
                a[mi][1] = f2tf32(Ap[(r+8)*A_PITCH + kc]);
                a[mi][2] = f2tf32(Ap[r*A_PITCH + kc + 4]);
                a[mi][3] = f2tf32(Ap[(r+8)*A_PITCH + kc + 4]);
            }
            #pragma unroll
            for (int ni = 0; ni < 8; ni++) {
                int nn = n0w + ni*8 + g;
                b[ni][0] = f2tf32(Bp[(ks*8 + tg)*B_PITCH + nn]);
                b[ni][1] = f2tf32(Bp[(ks*8 + tg + 4)*B_PITCH + nn]);
            }
            #pragma unroll
            for (int mi = 0; mi < 2; mi++)
                #pragma unroll
                for (int ni = 0; ni < 8; ni++)
                    mma_tf32(c[mi][ni], a[mi], b[ni]);
        }
        __syncthreads();
    }

    // epilogue
    #pragma unroll
    for (int mi = 0; mi < 2; mi++) {
        #pragma unroll
        for (int ni = 0; ni < 8; ni++) {
            int cc = col0 + n0w + ni*8 + 2*tg;
            float bx = bias[cc], by = bias[cc+1];
            #pragma unroll
            for (int rr = 0; rr < 2; rr++) {
                int r = row0 + m0w + mi*16 + g + rr*8;
                float vx = (c[mi][ni][rr*2+0] + bx) * scale;
                float vy = (c[mi][ni][rr*2+1] + by) * scale;
                if (MODE == 0) {
                    float2 v = make_float2(vx, vy);
                    *(float2*)&out[(size_t)r * Dsz + cc] = v;
                } else {
                    int b_ = r >> 11, s_ = r & (Ssz-1);
                    int h_ = cc >> 6, dh = cc & (DHs-1);
                    size_t base = (((size_t)(b_*Hn + h_) * Ssz) + s_) * DHs;
                    if (MODE == 1) {
                        float2 v = make_float2(tf32f(vx), tf32f(vy));
                        *(float2*)&out[base + dh] = v;
                    } else {  // MODE 2: V, dh -> pi64(dh)
                        int p0 = ((dh & 7) << 3) | (dh >> 3);
                        out[base + p0]     = tf32f(vx);
                        out[base + p0 + 8] = tf32f(vy);
                    }
                }
            }
        }
    }
}

// ---------------------------------------------------------------------------
// Flash attention (R4 kernel, validated): tf32 MMA, vectorized fragments.
// Q fragments register-resident; relabel mma-k ks*8+tg <-> actual d tg*8+ks.
// Kt row = pi64(d), col = pi64(kv); S-loop reads row ks*8+tg (holds d tg*8+ks).
// Vs rows = actual kv (pure cp.async; V gmem cols pre-permuted pi64(dh)).
// Epilogue CHANGED vs R4: plain [B,S,D] fp32 (feeds R2-style final GEMM).
// ---------------------------------------------------------------------------
#define P68 68
#define KV_T 17408                      // 64*68*4 bytes per stage
#define ATTN_SMEM (2*KV_T + 3*KV_T + 128*P68*4)

__global__ __launch_bounds__(256, 1)
void attn_mma(const float* __restrict__ Q, const float* __restrict__ K,
              const float* __restrict__ V, float* __restrict__ O)
{
    extern __shared__ float sm[];
    float* Kt = sm;                      // [2][64][68]
    float* Vs = sm + 2*64*P68;           // [3][64][68]
    float* Ps = sm + 5*64*P68;           // [128][68]

    const int tid  = threadIdx.x;
    const int lane = tid & 31;
    const int warp = tid >> 5;
    const int g  = lane >> 2;
    const int tg = lane & 3;
    const int m0w = warp * 16;
    const int r0 = m0w + g;

    const int q0 = blockIdx.x * 128;
    const int h = blockIdx.y, b = blockIdx.z;
    const size_t base = ((size_t)(b*Hn + h)) * Ssz * DHs;
    const float* Qg = Q + base;
    const float* Kg = K + base;
    const float* Vg = V + base;

    // ---- Q fragments: 8 LDG.128, registers for all tiles ----
    float aqf[4][8];
    {
        const float* Qr0 = &Qg[(size_t)(q0 + r0) * DHs];
        const float* Qr1 = &Qg[(size_t)(q0 + r0 + 8) * DHs];
        *(float4*)&aqf[0][0] = *(const float4*)&Qr0[tg*8];
        *(float4*)&aqf[0][4] = *(const float4*)&Qr0[tg*8 + 4];
        *(float4*)&aqf[1][0] = *(const float4*)&Qr1[tg*8];
        *(float4*)&aqf[1][4] = *(const float4*)&Qr1[tg*8 + 4];
        *(float4*)&aqf[2][0] = *(const float4*)&Qr0[(tg+4)*8];
        *(float4*)&aqf[2][4] = *(const float4*)&Qr0[(tg+4)*8 + 4];
        *(float4*)&aqf[3][0] = *(const float4*)&Qr1[(tg+4)*8];
        *(float4*)&aqf[3][4] = *(const float4*)&Qr1[(tg+4)*8 + 4];
    }

    float kreg[4][4];   // K prefetch registers

    auto ldg_K = [&](int t0) {
        #pragma unroll
        for (int i = 0; i < 4; i++) {
            int idx = tid + i*256;
            int r = idx >> 4, c4 = idx & 15;
            *(float4*)kreg[i] = *(const float4*)&Kg[(size_t)(t0 + r) * DHs + c4*4];
        }
    };
    auto sts_K = [&](float* dst) {
        #pragma unroll
        for (int i = 0; i < 4; i++) {
            int idx = tid + i*256;
            int r = idx >> 4, c4 = idx & 15;
            int pcol = ((r & 7) << 3) | (r >> 3);          // pi64(kv)
            int dbase = ((c4 & 1) << 5);
            int dlow  = c4 >> 1;
            #pragma unroll
            for (int j = 0; j < 4; j++)
                dst[(dbase + j*8 + dlow)*P68 + pcol] = kreg[i][j];   // row = pi64(d)
        }
    };
    auto cpa_V = [&](int t0, float* dst) {
        #pragma unroll
        for (int i = 0; i < 4; i++) {
            int idx = tid + i*256;
            int r = idx >> 4, c4 = idx & 15;
            cp_async16(&dst[r*P68 + c4*4], &Vg[(size_t)(t0 + r) * DHs + c4*4]);
        }
    };

    // ---- prologue ----
    cpa_V(0, Vs);             CP_COMMIT();
    ldg_K(0);  sts_K(Kt);
    cpa_V(64, Vs + 64*P68);   CP_COMMIT();
    ldg_K(64);
    CP_WAIT1();
    __syncthreads();

    float o[8][4] = {};
    float m0 = -1e30f, m1 = -1e30f, l0 = 0.0f, l1 = 0.0f;

    const int NTILE = Ssz / 64;   // 32
    for (int t = 0; t < NTILE; t++) {
        const int kp = t & 1;
        const float* Ktp = Kt + kp*64*P68;
        const float* Vsp = Vs + (t % 3)*64*P68;

        // ---- S = Q @ K^T ----
        float s[8][4] = {};
        #pragma unroll
        for (int ks = 0; ks < 8; ks++) {
            float b0[8], b1[8];
            const float* Kr0 = &Ktp[(ks*8 + tg)*P68 + g*8];
            const float* Kr1 = &Ktp[(ks*8 + tg + 4)*P68 + g*8];
            *(float4*)&b0[0] = *(const float4*)&Kr0[0];
            *(float4*)&b0[4] = *(const float4*)&Kr0[4];
            *(float4*)&b1[0] = *(const float4*)&Kr1[0];
            *(float4*)&b1[4] = *(const float4*)&Kr1[4];
            unsigned a[4] = { __float_as_uint(aqf[0][ks]), __float_as_uint(aqf[1][ks]),
                              __float_as_uint(aqf[2][ks]), __float_as_uint(aqf[3][ks]) };
            #pragma unroll
            for (int nt = 0; nt < 8; nt++) {
                unsigned bf[2] = { __float_as_uint(b0[nt]), __float_as_uint(b1[nt]) };
                mma_tf32(s[nt], a, bf);
            }
        }

        // K_{t+1} -> smem (other stage; visibility via end-of-iter sync)
        if (t + 1 < NTILE) sts_K(Kt + (kp^1)*64*P68);

        // ---- online softmax (base-2; Q pre-scaled by log2e/8) ----
        float rm0 = -1e30f, rm1 = -1e30f;
        #pragma unroll
        for (int nt = 0; nt < 8; nt++) {
            rm0 = fmaxf(rm0, fmaxf(s[nt][0], s[nt][1]));
            rm1 = fmaxf(rm1, fmaxf(s[nt][2], s[nt][3]));
        }
        rm0 = fmaxf(rm0, __shfl_xor_sync(0xffffffffu, rm0, 1));
        rm0 = fmaxf(rm0, __shfl_xor_sync(0xffffffffu, rm0, 2));
        rm1 = fmaxf(rm1, __shfl_xor_sync(0xffffffffu, rm1, 1));
        rm1 = fmaxf(rm1, __shfl_xor_sync(0xffffffffu, rm1, 2));

        float mn0 = fmaxf(m0, rm0), mn1 = fmaxf(m1, rm1);
        float al0 = ex2(m0 - mn0), al1 = ex2(m1 - mn1);
        m0 = mn0; m1 = mn1;

        float rs0 = 0.0f, rs1 = 0.0f;
        #pragma unroll
        for (int nt = 0; nt < 8; nt++) {
            s[nt][0] = ex2(s[nt][0] - m0);
            s[nt][1] = ex2(s[nt][1] - m0);
            s[nt][2] = ex2(s[nt][2] - m1);
            s[nt][3] = ex2(s[nt][3] - m1);
            rs0 += s[nt][0] + s[nt][1];
            rs1 += s[nt][2] + s[nt][3];
        }
        rs0 += __shfl_xor_sync(0xffffffffu, rs0, 1);
        rs0 += __shfl_xor_sync(0xffffffffu, rs0, 2);
        rs1 += __shfl_xor_sync(0xffffffffu, rs1, 1);
        rs1 += __shfl_xor_sync(0xffffffffu, rs1, 2);

        l0 = l0 * al0 + rs0;
        l1 = l1 * al1 + rs1;
        #pragma unroll
        for (int nt = 0; nt < 8; nt++) {
            o[nt][0] *= al0; o[nt][1] *= al0;
            o[nt][2] *= al1; o[nt][3] *= al1;
        }

        // ---- P -> smem (warp-local rows), tf32-cvt'd ----
        __syncwarp();
        #pragma unroll
        for (int nt = 0; nt < 8; nt++) {
            float2 p01 = make_float2(tf32f(s[nt][0]), tf32f(s[nt][1]));
            float2 p23 = make_float2(tf32f(s[nt][2]), tf32f(s[nt][3]));
            *(float2*)&Ps[r0*P68 + nt*8 + 2*tg]       = p01;
            *(float2*)&Ps[(r0+8)*P68 + nt*8 + 2*tg]   = p23;
        }
        __syncwarp();

        // ---- O += P @ V ----
        float pa[4][8];
        {
            const float* Pr0 = &Ps[r0*P68];
            const float* Pr1 = &Ps[(r0+8)*P68];
            *(float4*)&pa[0][0] = *(const float4*)&Pr0[tg*8];
            *(float4*)&pa[0][4] = *(const float4*)&Pr0[tg*8 + 4];
            *(float4*)&pa[1][0] = *(const float4*)&Pr1[tg*8];
            *(float4*)&pa[1][4] = *(const float4*)&Pr1[tg*8 + 4];
            *(float4*)&pa[2][0] = *(const float4*)&Pr0[(tg+4)*8];
            *(float4*)&pa[2][4] = *(const float4*)&Pr0[(tg+4)*8 + 4];
            *(float4*)&pa[3][0] = *(const float4*)&Pr1[(tg+4)*8];
            *(float4*)&pa[3][4] = *(const float4*)&Pr1[(tg+4)*8 + 4];
        }
        #pragma unroll
        for (int ks = 0; ks < 8; ks++) {
            float b0[8], b1[8];
            const float* Vr0 = &Vsp[(tg*8 + ks)*P68 + g*8];
            const float* Vr1 = &Vsp[((tg+4)*8 + ks)*P68 + g*8];
            *(float4*)&b0[0] = *(const float4*)&Vr0[0];
            *(float4*)&b0[4] = *(const float4*)&Vr0[4];
            *(float4*)&b1[0] = *(const float4*)&Vr1[0];
            *(float4*)&b1[4] = *(const float4*)&Vr1[4];
            unsigned a[4] = { __float_as_uint(pa[0][ks]), __float_as_uint(pa[1][ks]),
                              __float_as_uint(pa[2][ks]), __float_as_uint(pa[3][ks]) };
            #pragma unroll
            for (int nt = 0; nt < 8; nt++) {
                unsigned bf[2] = { __float_as_uint(b0[nt]), __float_as_uint(b1[nt]) };
                mma_tf32(o[nt], a, bf);
            }
        }

        // ---- prefetch tile t+2 ----
        if (t + 2 < NTILE) {
            cpa_V((t+2)*64, Vs + ((t+2) % 3)*64*P68);
            CP_COMMIT();
            ldg_K((t+2)*64);
        }
        if (t + 2 < NTILE) { CP_WAIT1(); } else { CP_WAIT0(); }
        __syncthreads();
    }

    // ---- normalize + write O: plain [B,S,H*DH] fp32 (final GEMM cvt's itself) ----
    float inv0 = 1.0f / l0, inv1 = 1.0f / l1;
    size_t ob0 = ((size_t)(b*Ssz + q0 + r0)) * Dsz + h*DHs;
    size_t ob1 = ((size_t)(b*Ssz + q0 + r0 + 8)) * Dsz + h*DHs;
    #pragma unroll
    for (int nt = 0; nt < 8; nt++) {
        int n = nt*8 + 2*tg;
        float2 va = make_float2(o[nt][0]*inv0, o[nt][1]*inv0);
        float2 vb = make_float2(o[nt][2]*inv1, o[nt][3]*inv1);
        *(float2*)&O[ob0 + n] = va;
        *(float2*)&O[ob1 + n] = vb;
    }
}

// ---------------------------------------------------------------------------

extern "C" void kernel_launch(void* const* d_in, const int* in_sizes, int n_in,
                              void* d_out, int out_size)
{
    (void)in_sizes; (void)n_in; (void)out_size;
    const float* queries = (const float*)d_in[0];
    const float* keys    = (const float*)d_in[1];
    const float* values  = (const float*)d_in[2];
    const float* Wq = (const float*)d_in[3];
    const float* bq = (const float*)d_in[4];
    const float* Wk = (const float*)d_in[5];
    const float* bk = (const float*)d_in[6];
    const float* Wv = (const float*)d_in[7];
    const float* bv = (const float*)d_in[8];
    const float* Wo = (const float*)d_in[9];
    const float* bo = (const float*)d_in[10];
    float* out = (float*)d_out;

    void *pq, *pk, *pv, *po;
    cudaGetSymbolAddress(&pq, g_q);
    cudaGetSymbolAddress(&pk, g_k);
    cudaGetSymbolAddress(&pv, g_v);
    cudaGetSymbolAddress(&po, g_o);

    cudaFuncSetAttribute(gemm_tf32<0>, cudaFuncAttributeMaxDynamicSharedMemorySize, GEMM_SMEM);
    cudaFuncSetAttribute(gemm_tf32<1>, cudaFuncAttributeMaxDynamicSharedMemorySize, GEMM_SMEM);
    cudaFuncSetAttribute(gemm_tf32<2>, cudaFuncAttributeMaxDynamicSharedMemorySize, GEMM_SMEM);
    cudaFuncSetAttribute(attn_mma,     cudaFuncAttributeMaxDynamicSharedMemorySize, ATTN_SMEM);

    dim3 ggrid(Dsz/128, Mrows/128);   // (8, 32)
    const float qscale = 0.125f * 1.4426950408889634f;   // log2e / sqrt(64)

    gemm_tf32<1><<<ggrid, 256, GEMM_SMEM>>>(queries, Wq, bq, (float*)pq, qscale);
    gemm_tf32<1><<<ggrid, 256, GEMM_SMEM>>>(keys,    Wk, bk, (float*)pk, 1.0f);
    gemm_tf32<2><<<ggrid, 256, GEMM_SMEM>>>(values,  Wv, bv, (float*)pv, 1.0f);

    dim3 agrid(Ssz/128, Hn, Bsz);     // (16, 16, 2)
    attn_mma<<<agrid, 256, ATTN_SMEM>>>((const float*)pq, (const float*)pk,
                                        (const float*)pv, (float*)po);

    gemm_tf32<0><<<ggrid, 256, GEMM_SMEM>>>((const float*)po, Wo, bo, out, 1.0f);
}

// round 6
// speedup vs baseline: 1.7409x; 1.5206x over previous
#include <cuda_runtime.h>
#include <math.h>

#define Bsz 2
#define Ssz 2048
#define Dsz 1024
#define Hn  16
#define DHs 64
#define Mrows (Bsz*Ssz)

// Scratch (static device globals; no runtime allocation)
__device__ float g_q[Mrows*Dsz];    // [B,H,S,64]  tf32-rounded, plain dh
__device__ float g_k[Mrows*Dsz];    // [B,H,64,S]  TRANSPOSED (d-major), tf32-rounded
__device__ float g_v[Mrows*Dsz];    // [B,H,S,64]  tf32-rounded, dh -> pi64(dh)
__device__ float g_o[Mrows*Dsz];    // [M,1024]    fp32 plain

// ---------------------------------------------------------------------------
// helpers
// ---------------------------------------------------------------------------
__device__ __forceinline__ unsigned f2tf32(float x) {
    unsigned r;
    asm("cvt.rna.tf32.f32 %0, %1;" : "=r"(r) : "f"(x));
    return r;
}
__device__ __forceinline__ float tf32f(float x) { return __uint_as_float(f2tf32(x)); }

__device__ __forceinline__ float ex2(float x) {
    float r; asm("ex2.approx.ftz.f32 %0, %1;" : "=f"(r) : "f"(x)); return r;
}

__device__ __forceinline__ void mma_tf32(float* c, const unsigned* a, const unsigned* b) {
    asm volatile(
        "mma.sync.aligned.m16n8k8.row.col.f32.tf32.tf32.f32 "
        "{%0,%1,%2,%3}, {%4,%5,%6,%7}, {%8,%9}, {%0,%1,%2,%3};"
        : "+f"(c[0]), "+f"(c[1]), "+f"(c[2]), "+f"(c[3])
        : "r"(a[0]), "r"(a[1]), "r"(a[2]), "r"(a[3]), "r"(b[0]), "r"(b[1]));
}

__device__ __forceinline__ void cp_async16(void* smem, const void* gmem) {
    unsigned s = (unsigned)__cvta_generic_to_shared(smem);
    asm volatile("cp.async.cg.shared.global [%0], [%1], 16;" :: "r"(s), "l"(gmem));
}
#define CP_COMMIT() asm volatile("cp.async.commit_group;")
#define CP_WAIT1()  asm volatile("cp.async.wait_group 1;")
#define CP_WAIT0()  asm volatile("cp.async.wait_group 0;")

// ---------------------------------------------------------------------------
// TF32 GEMM — EXACT R2 main loop (measured-good). Epilogue modes:
// MODE 0: plain [M,1024] fp32 float2 stores (final projection output)
// MODE 1: Q:  head-split [B,H,S,64], tf32-rounded, plain dh
// MODE 2: V:  head-split, tf32-rounded, dh -> pi64(dh) = ((dh&7)<<3)|(dh>>3)
// MODE 3: K:  head-split TRANSPOSED [B,H,64,S], tf32-rounded
// ---------------------------------------------------------------------------
#define A_PITCH 36
#define B_PITCH 132
#define GEMM_SMEM ((2*128*A_PITCH + 2*32*B_PITCH) * 4)

template<int MODE>
__global__ __launch_bounds__(256, 2)
void gemm_tf32(const float* __restrict__ X, const float* __restrict__ W,
               const float* __restrict__ bias, float* __restrict__ out,
               float scale)
{
    extern __shared__ float sm[];
    float* As = sm;                       // [2][128][36]
    float* Bs = sm + 2*128*A_PITCH;       // [2][32][132]

    const int tid  = threadIdx.x;
    const int lane = tid & 31;
    const int warp = tid >> 5;
    const int g  = lane >> 2;
    const int tg = lane & 3;
    const int m0w = (warp >> 1) * 32;
    const int n0w = (warp & 1) * 64;
    const int row0 = blockIdx.y * 128;
    const int col0 = blockIdx.x * 128;

    float c[2][8][4] = {};

    auto load_stage = [&](int kt, int p) {
        float* Ad = As + p*128*A_PITCH;
        float* Bd = Bs + p*32*B_PITCH;
        #pragma unroll
        for (int i = 0; i < 4; i++) {
            int idx = tid + i*256;
            int r = idx >> 3, c4 = idx & 7;
            cp_async16(&Ad[r*A_PITCH + c4*4], &X[(size_t)(row0 + r)*Dsz + kt*32 + c4*4]);
        }
        #pragma unroll
        for (int i = 0; i < 4; i++) {
            int idx = tid + i*256;
            int r = idx >> 5, c4 = idx & 31;
            cp_async16(&Bd[r*B_PITCH + c4*4], &W[(size_t)(kt*32 + r)*Dsz + col0 + c4*4]);
        }
    };

    load_stage(0, 0);
    CP_COMMIT();

    const int NT = Dsz / 32;
    for (int kt = 0; kt < NT; kt++) {
        int p = kt & 1;
        if (kt + 1 < NT) {
            load_stage(kt + 1, p ^ 1);
            CP_COMMIT();
            CP_WAIT1();
        } else {
            CP_WAIT0();
        }
        __syncthreads();

        const float* Ap = As + p*128*A_PITCH;
        const float* Bp = Bs + p*32*B_PITCH;
        #pragma unroll
        for (int ks = 0; ks < 4; ks++) {
            unsigned a[2][4], b[8][2];
            #pragma unroll
            for (int mi = 0; mi < 2; mi++) {
                int r = m0w + mi*16 + g;
                int kc = ks*8 + tg;
                a[mi][0] = f2tf32(Ap[r*A_PITCH + kc]);
                a[mi][1] = f2tf32(Ap[(r+8)*A_PITCH + kc]);
                a[mi][2] = f2tf32(Ap[r*A_PITCH + kc + 4]);
                a[mi][3] = f2tf32(Ap[(r+8)*A_PITCH + kc + 4]);
            }
            #pragma unroll
            for (int ni = 0; ni < 8; ni++) {
                int nn = n0w + ni*8 + g;
                b[ni][0] = f2tf32(Bp[(ks*8 + tg)*B_PITCH + nn]);
                b[ni][1] = f2tf32(Bp[(ks*8 + tg + 4)*B_PITCH + nn]);
            }
            #pragma unroll
            for (int mi = 0; mi < 2; mi++)
                #pragma unroll
                for (int ni = 0; ni < 8; ni++)
                    mma_tf32(c[mi][ni], a[mi], b[ni]);
        }
        __syncthreads();
    }

    // epilogue
    #pragma unroll
    for (int mi = 0; mi < 2; mi++) {
        #pragma unroll
        for (int ni = 0; ni < 8; ni++) {
            int cc = col0 + n0w + ni*8 + 2*tg;
            float bx = bias[cc], by = bias[cc+1];
            #pragma unroll
            for (int rr = 0; rr < 2; rr++) {
                int r = row0 + m0w + mi*16 + g + rr*8;
                float vx = (c[mi][ni][rr*2+0] + bx) * scale;
                float vy = (c[mi][ni][rr*2+1] + by) * scale;
                if (MODE == 0) {
                    float2 v = make_float2(vx, vy);
                    *(float2*)&out[(size_t)r * Dsz + cc] = v;
                } else {
                    int b_ = r >> 11, s_ = r & (Ssz-1);
                    int h_ = cc >> 6, dh = cc & (DHs-1);
                    if (MODE == 1) {
                        size_t base = (((size_t)(b_*Hn + h_) * Ssz) + s_) * DHs;
                        float2 v = make_float2(tf32f(vx), tf32f(vy));
                        *(float2*)&out[base + dh] = v;
                    } else if (MODE == 2) {  // V: dh -> pi64(dh)
                        size_t base = (((size_t)(b_*Hn + h_) * Ssz) + s_) * DHs;
                        int p0 = ((dh & 7) << 3) | (dh >> 3);
                        out[base + p0]     = tf32f(vx);
                        out[base + p0 + 8] = tf32f(vy);
                    } else {                  // MODE 3: K transposed [b,h,d,s]
                        size_t kb = (((size_t)(b_*Hn + h_) * DHs) + dh) * Ssz + s_;
                        out[kb]       = tf32f(vx);
                        out[kb + Ssz] = tf32f(vy);
                    }
                }
            }
        }
    }
}

// ---------------------------------------------------------------------------
// Flash attention, tf32 MMA, conflict-free vectorized fragments, 2 CTAs/SM.
// K gmem TRANSPOSED [b,h,d,s] -> Kt via pure cp.async (rows = d, cols = kv).
// V gmem [b,h,s,pi64(dh)]     -> Vs via pure cp.async (rows = kv).
// Relabels: mma-k j <-> actual d = j*8+ks (Q regs);
//   S' cols n' with actual kv = pi64(n') -> K frag reads are LDS.128;
//   PV contraction over n' with V's pi64(dh) -> V frag reads are LDS.128;
//   output col mapping lands plain (epilogue unchanged).
// XOR chunk swizzle sigma in {0,1,4,5} -> all frag LDS.128 conflict-free.
// smem: Kt[2][64][64] + Vs[2][64][64] + Ps[128][68] = 100,352 B.
// ---------------------------------------------------------------------------
#define P68 68
#define ATTN_SMEM ((2*64*64 + 2*64*64 + 128*P68) * 4)   // 100,352 B

__global__ __launch_bounds__(256, 2)
void attn_mma(const float* __restrict__ Q, const float* __restrict__ K,
              const float* __restrict__ V, float* __restrict__ O)
{
    extern __shared__ float sm[];
    float* Kt = sm;                      // [2][64][64]
    float* Vs = sm + 2*64*64;            // [2][64][64]
    float* Ps = sm + 4*64*64;            // [128][68]

    const int tid  = threadIdx.x;
    const int lane = tid & 31;
    const int warp = tid >> 5;
    const int g  = lane >> 2;
    const int tg = lane & 3;
    const int m0w = warp * 16;
    const int r0 = m0w + g;

    const int q0 = blockIdx.x * 128;
    const int h = blockIdx.y, b = blockIdx.z;
    const size_t baseQ = ((size_t)(b*Hn + h)) * Ssz * DHs;
    const float* Qg = Q + baseQ;
    const float* Kg = K + baseQ;   // [64][Ssz] transposed layout, same total offset
    const float* Vg = V + baseQ;

    // fragment-read swizzle constant (same for K and V reads; depends on tg)
    const int sig = (tg & 1) | ((tg & 2) << 1);
    const int pk0 = ((2*g)     ^ sig) << 2;   // word offset of logical chunk 2g
    const int pk1 = ((2*g + 1) ^ sig) << 2;   // word offset of logical chunk 2g+1

    // ---- Q fragments: 8 LDG.128, registers for all tiles ----
    float aqf[4][8];
    {
        const float* Qr0 = &Qg[(size_t)(q0 + r0) * DHs];
        const float* Qr1 = &Qg[(size_t)(q0 + r0 + 8) * DHs];
        *(float4*)&aqf[0][0] = *(const float4*)&Qr0[tg*8];
        *(float4*)&aqf[0][4] = *(const float4*)&Qr0[tg*8 + 4];
        *(float4*)&aqf[1][0] = *(const float4*)&Qr1[tg*8];
        *(float4*)&aqf[1][4] = *(const float4*)&Qr1[tg*8 + 4];
        *(float4*)&aqf[2][0] = *(const float4*)&Qr0[(tg+4)*8];
        *(float4*)&aqf[2][4] = *(const float4*)&Qr0[(tg+4)*8 + 4];
        *(float4*)&aqf[3][0] = *(const float4*)&Qr1[(tg+4)*8];
        *(float4*)&aqf[3][4] = *(const float4*)&Qr1[(tg+4)*8 + 4];
    }

    // both K and V tiles are pure cp.async, 2-stage
    auto load_tile = [&](int t0, int stage) {
        float* Kd = Kt + stage*64*64;
        float* Vd = Vs + stage*64*64;
        #pragma unroll
        for (int i = 0; i < 4; i++) {
            int idx = tid + i*256;
            int r = idx >> 4, c = idx & 15;
            int sk = ((r >> 3) & 1) | (((r >> 3) & 2) << 1);   // sigma_k(d row)
            cp_async16(&Kd[r*64 + ((c ^ sk) << 2)],
                       &Kg[(size_t)r * Ssz + t0 + (c << 2)]);
            int sv = (r & 1) | ((r & 2) << 1);                  // sigma_v(kv row)
            cp_async16(&Vd[r*64 + ((c ^ sv) << 2)],
                       &Vg[(size_t)(t0 + r) * DHs + (c << 2)]);
        }
    };

    // ---- prologue: stages 0,1 ----
    load_tile(0, 0);   CP_COMMIT();
    load_tile(64, 1);  CP_COMMIT();

    float o[8][4] = {};
    float m0 = -1e30f, m1 = -1e30f, l0 = 0.0f, l1 = 0.0f;

    const int NTILE = Ssz / 64;   // 32
    for (int t = 0; t < NTILE; t++) {
        if (t + 1 < NTILE) { CP_WAIT1(); } else { CP_WAIT0(); }
        __syncthreads();

        const float* Ktp = Kt + (t & 1)*64*64;
        const float* Vsp = Vs + (t & 1)*64*64;

        // ---- S' = Q @ K^T (cols relabeled by pi64) ----
        float s[8][4] = {};
        #pragma unroll
        for (int ks = 0; ks < 8; ks++) {
            float b0[8], b1[8];
            const float* Kr0 = &Ktp[(tg*8 + ks)*64];        // actual d = tg*8+ks
            const float* Kr1 = &Ktp[((tg+4)*8 + ks)*64];    // actual d = (tg+4)*8+ks
            *(float4*)&b0[0] = *(const float4*)&Kr0[pk0];
            *(float4*)&b0[4] = *(const float4*)&Kr0[pk1];
            *(float4*)&b1[0] = *(const float4*)&Kr1[pk0];
            *(float4*)&b1[4] = *(const float4*)&Kr1[pk1];
            unsigned a[4] = { __float_as_uint(aqf[0][ks]), __float_as_uint(aqf[1][ks]),
                              __float_as_uint(aqf[2][ks]), __float_as_uint(aqf[3][ks]) };
            #pragma unroll
            for (int nt = 0; nt < 8; nt++) {
                unsigned bf[2] = { __float_as_uint(b0[nt]), __float_as_uint(b1[nt]) };
                mma_tf32(s[nt], a, bf);
            }
        }

        // ---- online softmax (base-2; Q pre-scaled by log2e/8); perm-invariant ----
        float rm0 = -1e30f, rm1 = -1e30f;
        #pragma unroll
        for (int nt = 0; nt < 8; nt++) {
            rm0 = fmaxf(rm0, fmaxf(s[nt][0], s[nt][1]));
            rm1 = fmaxf(rm1, fmaxf(s[nt][2], s[nt][3]));
        }
        rm0 = fmaxf(rm0, __shfl_xor_sync(0xffffffffu, rm0, 1));
        rm0 = fmaxf(rm0, __shfl_xor_sync(0xffffffffu, rm0, 2));
        rm1 = fmaxf(rm1, __shfl_xor_sync(0xffffffffu, rm1, 1));
        rm1 = fmaxf(rm1, __shfl_xor_sync(0xffffffffu, rm1, 2));

        float mn0 = fmaxf(m0, rm0), mn1 = fmaxf(m1, rm1);
        float al0 = ex2(m0 - mn0), al1 = ex2(m1 - mn1);
        m0 = mn0; m1 = mn1;

        float rs0 = 0.0f, rs1 = 0.0f;
        #pragma unroll
        for (int nt = 0; nt < 8; nt++) {
            s[nt][0] = ex2(s[nt][0] - m0);
            s[nt][1] = ex2(s[nt][1] - m0);
            s[nt][2] = ex2(s[nt][2] - m1);
            s[nt][3] = ex2(s[nt][3] - m1);
            rs0 += s[nt][0] + s[nt][1];
            rs1 += s[nt][2] + s[nt][3];
        }
        rs0 += __shfl_xor_sync(0xffffffffu, rs0, 1);
        rs0 += __shfl_xor_sync(0xffffffffu, rs0, 2);
        rs1 += __shfl_xor_sync(0xffffffffu, rs1, 1);
        rs1 += __shfl_xor_sync(0xffffffffu, rs1, 2);

        l0 = l0 * al0 + rs0;
        l1 = l1 * al1 + rs1;
        #pragma unroll
        for (int nt = 0; nt < 8; nt++) {
            o[nt][0] *= al0; o[nt][1] *= al0;
            o[nt][2] *= al1; o[nt][3] *= al1;
        }

        // ---- P' -> smem (warp-local rows), tf32-cvt'd ----
        __syncwarp();
        #pragma unroll
        for (int nt = 0; nt < 8; nt++) {
            float2 p01 = make_float2(tf32f(s[nt][0]), tf32f(s[nt][1]));
            float2 p23 = make_float2(tf32f(s[nt][2]), tf32f(s[nt][3]));
            *(float2*)&Ps[r0*P68 + nt*8 + 2*tg]       = p01;
            *(float2*)&Ps[(r0+8)*P68 + nt*8 + 2*tg]   = p23;
        }
        __syncwarp();

        // ---- O += P' @ V(perm) ----
        float pa[4][8];
        {
            const float* Pr0 = &Ps[r0*P68];
            const float* Pr1 = &Ps[(r0+8)*P68];
            *(float4*)&pa[0][0] = *(const float4*)&Pr0[tg*8];
            *(float4*)&pa[0][4] = *(const float4*)&Pr0[tg*8 + 4];
            *(float4*)&pa[1][0] = *(const float4*)&Pr1[tg*8];
            *(float4*)&pa[1][4] = *(const float4*)&Pr1[tg*8 + 4];
            *(float4*)&pa[2][0] = *(const float4*)&Pr0[(tg+4)*8];
            *(float4*)&pa[2][4] = *(const float4*)&Pr0[(tg+4)*8 + 4];
            *(float4*)&pa[3][0] = *(const float4*)&Pr1[(tg+4)*8];
            *(float4*)&pa[3][4] = *(const float4*)&Pr1[(tg+4)*8 + 4];
        }
        #pragma unroll
        for (int ks = 0; ks < 8; ks++) {
            float b0[8], b1[8];
            const float* Vr0 = &Vsp[(ks*8 + tg)*64];        // actual kv = ks*8+tg
            const float* Vr1 = &Vsp[(ks*8 + tg + 4)*64];    // actual kv = ks*8+tg+4
            *(float4*)&b0[0] = *(const float4*)&Vr0[pk0];
            *(float4*)&b0[4] = *(const float4*)&Vr0[pk1];
            *(float4*)&b1[0] = *(const float4*)&Vr1[pk0];
            *(float4*)&b1[4] = *(const float4*)&Vr1[pk1];
            unsigned a[4] = { __float_as_uint(pa[0][ks]), __float_as_uint(pa[1][ks]),
                              __float_as_uint(pa[2][ks]), __float_as_uint(pa[3][ks]) };
            #pragma unroll
            for (int nt = 0; nt < 8; nt++) {
                unsigned bf[2] = { __float_as_uint(b0[nt]), __float_as_uint(b1[nt]) };
                mma_tf32(o[nt], a, bf);
            }
        }

        // ---- all warps done with this stage; prefetch t+2 into it ----
        __syncthreads();
        if (t + 2 < NTILE) {
            load_tile((t+2)*64, t & 1);
            CP_COMMIT();
        }
    }

    // ---- normalize + write O: plain [B,S,H*DH] fp32 ----
    float inv0 = 1.0f / l0, inv1 = 1.0f / l1;
    size_t ob0 = ((size_t)(b*Ssz + q0 + r0)) * Dsz + h*DHs;
    size_t ob1 = ((size_t)(b*Ssz + q0 + r0 + 8)) * Dsz + h*DHs;
    #pragma unroll
    for (int nt = 0; nt < 8; nt++) {
        int n = nt*8 + 2*tg;
        float2 va = make_float2(o[nt][0]*inv0, o[nt][1]*inv0);
        float2 vb = make_float2(o[nt][2]*inv1, o[nt][3]*inv1);
        *(float2*)&O[ob0 + n] = va;
        *(float2*)&O[ob1 + n] = vb;
    }
}

// ---------------------------------------------------------------------------

extern "C" void kernel_launch(void* const* d_in, const int* in_sizes, int n_in,
                              void* d_out, int out_size)
{
    (void)in_sizes; (void)n_in; (void)out_size;
    const float* queries = (const float*)d_in[0];
    const float* keys    = (const float*)d_in[1];
    const float* values  = (const float*)d_in[2];
    const float* Wq = (const float*)d_in[3];
    const float* bq = (const float*)d_in[4];
    const float* Wk = (const float*)d_in[5];
    const float* bk = (const float*)d_in[6];
    const float* Wv = (const float*)d_in[7];
    const float* bv = (const float*)d_in[8];
    const float* Wo = (const float*)d_in[9];
    const float* bo = (const float*)d_in[10];
    float* out = (float*)d_out;

    void *pq, *pk, *pv, *po;
    cudaGetSymbolAddress(&pq, g_q);
    cudaGetSymbolAddress(&pk, g_k);
    cudaGetSymbolAddress(&pv, g_v);
    cudaGetSymbolAddress(&po, g_o);

    cudaFuncSetAttribute(gemm_tf32<0>, cudaFuncAttributeMaxDynamicSharedMemorySize, GEMM_SMEM);
    cudaFuncSetAttribute(gemm_tf32<1>, cudaFuncAttributeMaxDynamicSharedMemorySize, GEMM_SMEM);
    cudaFuncSetAttribute(gemm_tf32<2>, cudaFuncAttributeMaxDynamicSharedMemorySize, GEMM_SMEM);
    cudaFuncSetAttribute(gemm_tf32<3>, cudaFuncAttributeMaxDynamicSharedMemorySize, GEMM_SMEM);
    cudaFuncSetAttribute(attn_mma,     cudaFuncAttributeMaxDynamicSharedMemorySize, ATTN_SMEM);

    dim3 ggrid(Dsz/128, Mrows/128);   // (8, 32)
    const float qscale = 0.125f * 1.4426950408889634f;   // log2e / sqrt(64)

    gemm_tf32<1><<<ggrid, 256, GEMM_SMEM>>>(queries, Wq, bq, (float*)pq, qscale);
    gemm_tf32<3><<<ggrid, 256, GEMM_SMEM>>>(keys,    Wk, bk, (float*)pk, 1.0f);
    gemm_tf32<2><<<ggrid, 256, GEMM_SMEM>>>(values,  Wv, bv, (float*)pv, 1.0f);

    dim3 agrid(Ssz/128, Hn, Bsz);     // (16, 16, 2)
    attn_mma<<<agrid, 256, ATTN_SMEM>>>((const float*)pq, (const float*)pk,
                                        (const float*)pv, (float*)po);

    gemm_tf32<0><<<ggrid, 256, GEMM_SMEM>>>((const float*)po, Wo, bo, out, 1.0f);
}

// round 7
// speedup vs baseline: 1.8135x; 1.0417x over previous
#include <cuda_runtime.h>
#include <math.h>

#define Bsz 2
#define Ssz 2048
#define Dsz 1024
#define Hn  16
#define DHs 64
#define Mrows (Bsz*Ssz)

// Scratch (static device globals; no runtime allocation)
__device__ float g_wq[Dsz*Dsz];     // weights, tf32-rounded + pi64-permuted cols
__device__ float g_wk[Dsz*Dsz];
__device__ float g_wv[Dsz*Dsz];
__device__ float g_wo[Dsz*Dsz];
__device__ float g_q[Mrows*Dsz];    // [B,H,S,64]  tf32-rounded, plain dh
__device__ float g_k[Mrows*Dsz];    // [B,H,64,S]  TRANSPOSED (d-major), tf32-rounded
__device__ float g_v[Mrows*Dsz];    // [B,H,S,64]  tf32-rounded, dh -> pi64(dh)
__device__ float g_o[Mrows*Dsz];    // [M,1024]    fp32 plain

// ---------------------------------------------------------------------------
// helpers
// ---------------------------------------------------------------------------
__device__ __forceinline__ unsigned f2tf32(float x) {
    unsigned r;
    asm("cvt.rna.tf32.f32 %0, %1;" : "=r"(r) : "f"(x));
    return r;
}
__device__ __forceinline__ float tf32f(float x) { return __uint_as_float(f2tf32(x)); }

__device__ __forceinline__ float ex2(float x) {
    float r; asm("ex2.approx.ftz.f32 %0, %1;" : "=f"(r) : "f"(x)); return r;
}

__device__ __forceinline__ void mma_tf32(float* c, const unsigned* a, const unsigned* b) {
    asm volatile(
        "mma.sync.aligned.m16n8k8.row.col.f32.tf32.tf32.f32 "
        "{%0,%1,%2,%3}, {%4,%5,%6,%7}, {%8,%9}, {%0,%1,%2,%3};"
        : "+f"(c[0]), "+f"(c[1]), "+f"(c[2]), "+f"(c[3])
        : "r"(a[0]), "r"(a[1]), "r"(a[2]), "r"(a[3]), "r"(b[0]), "r"(b[1]));
}

__device__ __forceinline__ void cp_async16(void* smem, const void* gmem) {
    unsigned s = (unsigned)__cvta_generic_to_shared(smem);
    asm volatile("cp.async.cg.shared.global [%0], [%1], 16;" :: "r"(s), "l"(gmem));
}
#define CP_COMMIT() asm volatile("cp.async.commit_group;")
#define CP_WAIT1()  asm volatile("cp.async.wait_group 1;")
#define CP_WAIT0()  asm volatile("cp.async.wait_group 0;")

// ---------------------------------------------------------------------------
// Weight convert: tf32-rna round + pi64 column permute within 64-wide windows.
// pi64(x) = ((x&7)<<3)|(x>>3)  (involution). Validated in R4 (numerics passed).
// ---------------------------------------------------------------------------
__global__ void cvt_w(const float* __restrict__ in, float* __restrict__ out) {
    size_t base = ((size_t)blockIdx.x * 256 + threadIdx.x) * 4;
    float4 v = *(const float4*)&in[base];
    unsigned low = (unsigned)(base & 63);
    size_t p = (base & ~(size_t)63) + (((low & 7) << 3) | (low >> 3));
    out[p]      = tf32f(v.x);
    out[p + 8]  = tf32f(v.y);
    out[p + 16] = tf32f(v.z);
    out[p + 24] = tf32f(v.w);
}

// ---------------------------------------------------------------------------
// TF32 GEMM. A path = R2-scalar (measured-good). B path NEW:
//   W pre-permuted pi64 + tf32 -> B frags are 4 conflict-free LDS.128 per ks
//   (XOR chunk swizzle sigma(r) = (r&1)|((r&2)<<1), pitch 128), zero cvt.
//   b0[j] = stored col n0w+g*8+j = actual col n0w+j*8+g  -> ni=j mapping,
//   identical to R2's epilogue column formula (unchanged).
// MODE 0: plain [M,1024] fp32   MODE 1: Q head-split tf32
// MODE 2: V head-split tf32 pi64(dh)   MODE 3: K head-split TRANSPOSED tf32
// ---------------------------------------------------------------------------
#define A_PITCH 36
#define GEMM_SMEM ((2*128*A_PITCH + 2*32*128) * 4)   // 69,632 B

template<int MODE>
__global__ __launch_bounds__(256, 2)
void gemm_tf32(const float* __restrict__ X, const float* __restrict__ W,
               const float* __restrict__ bias, float* __restrict__ out,
               float scale)
{
    extern __shared__ float sm[];
    float* As = sm;                       // [2][128][36]
    float* Bs = sm + 2*128*A_PITCH;       // [2][32][128], XOR-swizzled chunks

    const int tid  = threadIdx.x;
    const int lane = tid & 31;
    const int warp = tid >> 5;
    const int g  = lane >> 2;
    const int tg = lane & 3;
    const int m0w = (warp >> 1) * 32;
    const int n0w = (warp & 1) * 64;
    const int row0 = blockIdx.y * 128;
    const int col0 = blockIdx.x * 128;

    // B fragment-read swizzle constants
    const int sig = (tg & 1) | ((tg & 2) << 1);
    const int pk0 = ((2*g)     ^ sig) << 2;
    const int pk1 = ((2*g + 1) ^ sig) << 2;

    float c[2][8][4] = {};

    auto load_stage = [&](int kt, int p) {
        float* Ad = As + p*128*A_PITCH;
        float* Bd = Bs + p*32*128;
        #pragma unroll
        for (int i = 0; i < 4; i++) {
            int idx = tid + i*256;
            int r = idx >> 3, c4 = idx & 7;
            cp_async16(&Ad[r*A_PITCH + c4*4], &X[(size_t)(row0 + r)*Dsz + kt*32 + c4*4]);
        }
        #pragma unroll
        for (int i = 0; i < 4; i++) {
            int idx = tid + i*256;
            int r = idx >> 5, c4 = idx & 31;
            int s = (r & 1) | ((r & 2) << 1);
            cp_async16(&Bd[r*128 + ((c4 ^ s) << 2)],
                       &W[(size_t)(kt*32 + r)*Dsz + col0 + c4*4]);
        }
    };

    load_stage(0, 0);
    CP_COMMIT();

    const int NT = Dsz / 32;
    for (int kt = 0; kt < NT; kt++) {
        int p = kt & 1;
        if (kt + 1 < NT) {
            load_stage(kt + 1, p ^ 1);
            CP_COMMIT();
            CP_WAIT1();
        } else {
            CP_WAIT0();
        }
        __syncthreads();

        const float* Ap = As + p*128*A_PITCH;
        const float* Bp = Bs + p*32*128;
        #pragma unroll
        for (int ks = 0; ks < 4; ks++) {
            // A fragments: R2 scalar path (in-loop tf32 cvt)
            unsigned a[2][4];
            #pragma unroll
            for (int mi = 0; mi < 2; mi++) {
                int r = m0w + mi*16 + g;
                int kc = ks*8 + tg;
                a[mi][0] = f2tf32(Ap[r*A_PITCH + kc]);
                a[mi][1] = f2tf32(Ap[(r+8)*A_PITCH + kc]);
                a[mi][2] = f2tf32(Ap[r*A_PITCH + kc + 4]);
                a[mi][3] = f2tf32(Ap[(r+8)*A_PITCH + kc + 4]);
            }
            // B fragments: 4 conflict-free LDS.128, zero cvt
            float b0[8], b1[8];
            const float* Br0 = &Bp[(ks*8 + tg)*128 + n0w];
            const float* Br1 = &Bp[(ks*8 + tg + 4)*128 + n0w];
            *(float4*)&b0[0] = *(const float4*)&Br0[pk0];
            *(float4*)&b0[4] = *(const float4*)&Br0[pk1];
            *(float4*)&b1[0] = *(const float4*)&Br1[pk0];
            *(float4*)&b1[4] = *(const float4*)&Br1[pk1];

            #pragma unroll
            for (int mi = 0; mi < 2; mi++)
                #pragma unroll
                for (int ni = 0; ni < 8; ni++) {
                    unsigned bf[2] = { __float_as_uint(b0[ni]), __float_as_uint(b1[ni]) };
                    mma_tf32(c[mi][ni], a[mi], bf);
                }
        }
        __syncthreads();
    }

    // epilogue (column mapping identical to R2: ni -> n0w + ni*8 + g)
    #pragma unroll
    for (int mi = 0; mi < 2; mi++) {
        #pragma unroll
        for (int ni = 0; ni < 8; ni++) {
            int cc = col0 + n0w + ni*8 + 2*tg;
            float bx = bias[cc], by = bias[cc+1];
            #pragma unroll
            for (int rr = 0; rr < 2; rr++) {
                int r = row0 + m0w + mi*16 + g + rr*8;
                float vx = (c[mi][ni][rr*2+0] + bx) * scale;
                float vy = (c[mi][ni][rr*2+1] + by) * scale;
                if (MODE == 0) {
                    float2 v = make_float2(vx, vy);
                    *(float2*)&out[(size_t)r * Dsz + cc] = v;
                } else {
                    int b_ = r >> 11, s_ = r & (Ssz-1);
                    int h_ = cc >> 6, dh = cc & (DHs-1);
                    if (MODE == 1) {
                        size_t base = (((size_t)(b_*Hn + h_) * Ssz) + s_) * DHs;
                        float2 v = make_float2(tf32f(vx), tf32f(vy));
                        *(float2*)&out[base + dh] = v;
                    } else if (MODE == 2) {  // V: dh -> pi64(dh)
                        size_t base = (((size_t)(b_*Hn + h_) * Ssz) + s_) * DHs;
                        int p0 = ((dh & 7) << 3) | (dh >> 3);
                        out[base + p0]     = tf32f(vx);
                        out[base + p0 + 8] = tf32f(vy);
                    } else {                  // MODE 3: K transposed [b,h,d,s]
                        size_t kb = (((size_t)(b_*Hn + h_) * DHs) + dh) * Ssz + s_;
                        out[kb]       = tf32f(vx);
                        out[kb + Ssz] = tf32f(vy);
                    }
                }
            }
        }
    }
}

// ---------------------------------------------------------------------------
// Flash attention — UNCHANGED from R6 (measured-good: 257.6 us).
// ---------------------------------------------------------------------------
#define P68 68
#define ATTN_SMEM ((2*64*64 + 2*64*64 + 128*P68) * 4)   // 100,352 B

__global__ __launch_bounds__(256, 2)
void attn_mma(const float* __restrict__ Q, const float* __restrict__ K,
              const float* __restrict__ V, float* __restrict__ O)
{
    extern __shared__ float sm[];
    float* Kt = sm;                      // [2][64][64]
    float* Vs = sm + 2*64*64;            // [2][64][64]
    float* Ps = sm + 4*64*64;            // [128][68]

    const int tid  = threadIdx.x;
    const int lane = tid & 31;
    const int warp = tid >> 5;
    const int g  = lane >> 2;
    const int tg = lane & 3;
    const int m0w = warp * 16;
    const int r0 = m0w + g;

    const int q0 = blockIdx.x * 128;
    const int h = blockIdx.y, b = blockIdx.z;
    const size_t baseQ = ((size_t)(b*Hn + h)) * Ssz * DHs;
    const float* Qg = Q + baseQ;
    const float* Kg = K + baseQ;
    const float* Vg = V + baseQ;

    const int sig = (tg & 1) | ((tg & 2) << 1);
    const int pk0 = ((2*g)     ^ sig) << 2;
    const int pk1 = ((2*g + 1) ^ sig) << 2;

    // ---- Q fragments: 8 LDG.128, registers for all tiles ----
    float aqf[4][8];
    {
        const float* Qr0 = &Qg[(size_t)(q0 + r0) * DHs];
        const float* Qr1 = &Qg[(size_t)(q0 + r0 + 8) * DHs];
        *(float4*)&aqf[0][0] = *(const float4*)&Qr0[tg*8];
        *(float4*)&aqf[0][4] = *(const float4*)&Qr0[tg*8 + 4];
        *(float4*)&aqf[1][0] = *(const float4*)&Qr1[tg*8];
        *(float4*)&aqf[1][4] = *(const float4*)&Qr1[tg*8 + 4];
        *(float4*)&aqf[2][0] = *(const float4*)&Qr0[(tg+4)*8];
        *(float4*)&aqf[2][4] = *(const float4*)&Qr0[(tg+4)*8 + 4];
        *(float4*)&aqf[3][0] = *(const float4*)&Qr1[(tg+4)*8];
        *(float4*)&aqf[3][4] = *(const float4*)&Qr1[(tg+4)*8 + 4];
    }

    auto load_tile = [&](int t0, int stage) {
        float* Kd = Kt + stage*64*64;
        float* Vd = Vs + stage*64*64;
        #pragma unroll
        for (int i = 0; i < 4; i++) {
            int idx = tid + i*256;
            int r = idx >> 4, c = idx & 15;
            int sk = ((r >> 3) & 1) | (((r >> 3) & 2) << 1);
            cp_async16(&Kd[r*64 + ((c ^ sk) << 2)],
                       &Kg[(size_t)r * Ssz + t0 + (c << 2)]);
            int sv = (r & 1) | ((r & 2) << 1);
            cp_async16(&Vd[r*64 + ((c ^ sv) << 2)],
                       &Vg[(size_t)(t0 + r) * DHs + (c << 2)]);
        }
    };

    load_tile(0, 0);   CP_COMMIT();
    load_tile(64, 1);  CP_COMMIT();

    float o[8][4] = {};
    float m0 = -1e30f, m1 = -1e30f, l0 = 0.0f, l1 = 0.0f;

    const int NTILE = Ssz / 64;   // 32
    for (int t = 0; t < NTILE; t++) {
        if (t + 1 < NTILE) { CP_WAIT1(); } else { CP_WAIT0(); }
        __syncthreads();

        const float* Ktp = Kt + (t & 1)*64*64;
        const float* Vsp = Vs + (t & 1)*64*64;

        // ---- S' = Q @ K^T (cols relabeled by pi64) ----
        float s[8][4] = {};
        #pragma unroll
        for (int ks = 0; ks < 8; ks++) {
            float b0[8], b1[8];
            const float* Kr0 = &Ktp[(tg*8 + ks)*64];
            const float* Kr1 = &Ktp[((tg+4)*8 + ks)*64];
            *(float4*)&b0[0] = *(const float4*)&Kr0[pk0];
            *(float4*)&b0[4] = *(const float4*)&Kr0[pk1];
            *(float4*)&b1[0] = *(const float4*)&Kr1[pk0];
            *(float4*)&b1[4] = *(const float4*)&Kr1[pk1];
            unsigned a[4] = { __float_as_uint(aqf[0][ks]), __float_as_uint(aqf[1][ks]),
                              __float_as_uint(aqf[2][ks]), __float_as_uint(aqf[3][ks]) };
            #pragma unroll
            for (int nt = 0; nt < 8; nt++) {
                unsigned bf[2] = { __float_as_uint(b0[nt]), __float_as_uint(b1[nt]) };
                mma_tf32(s[nt], a, bf);
            }
        }

        // ---- online softmax ----
        float rm0 = -1e30f, rm1 = -1e30f;
        #pragma unroll
        for (int nt = 0; nt < 8; nt++) {
            rm0 = fmaxf(rm0, fmaxf(s[nt][0], s[nt][1]));
            rm1 = fmaxf(rm1, fmaxf(s[nt][2], s[nt][3]));
        }
        rm0 = fmaxf(rm0, __shfl_xor_sync(0xffffffffu, rm0, 1));
        rm0 = fmaxf(rm0, __shfl_xor_sync(0xffffffffu, rm0, 2));
        rm1 = fmaxf(rm1, __shfl_xor_sync(0xffffffffu, rm1, 1));
        rm1 = fmaxf(rm1, __shfl_xor_sync(0xffffffffu, rm1, 2));

        float mn0 = fmaxf(m0, rm0), mn1 = fmaxf(m1, rm1);
        float al0 = ex2(m0 - mn0), al1 = ex2(m1 - mn1);
        m0 = mn0; m1 = mn1;

        float rs0 = 0.0f, rs1 = 0.0f;
        #pragma unroll
        for (int nt = 0; nt < 8; nt++) {
            s[nt][0] = ex2(s[nt][0] - m0);
            s[nt][1] = ex2(s[nt][1] - m0);
            s[nt][2] = ex2(s[nt][2] - m1);
            s[nt][3] = ex2(s[nt][3] - m1);
            rs0 += s[nt][0] + s[nt][1];
            rs1 += s[nt][2] + s[nt][3];
        }
        rs0 += __shfl_xor_sync(0xffffffffu, rs0, 1);
        rs0 += __shfl_xor_sync(0xffffffffu, rs0, 2);
        rs1 += __shfl_xor_sync(0xffffffffu, rs1, 1);
        rs1 += __shfl_xor_sync(0xffffffffu, rs1, 2);

        l0 = l0 * al0 + rs0;
        l1 = l1 * al1 + rs1;
        #pragma unroll
        for (int nt = 0; nt < 8; nt++) {
            o[nt][0] *= al0; o[nt][1] *= al0;
            o[nt][2] *= al1; o[nt][3] *= al1;
        }

        // ---- P' -> smem (warp-local rows), tf32-cvt'd ----
        __syncwarp();
        #pragma unroll
        for (int nt = 0; nt < 8; nt++) {
            float2 p01 = make_float2(tf32f(s[nt][0]), tf32f(s[nt][1]));
            float2 p23 = make_float2(tf32f(s[nt][2]), tf32f(s[nt][3]));
            *(float2*)&Ps[r0*P68 + nt*8 + 2*tg]       = p01;
            *(float2*)&Ps[(r0+8)*P68 + nt*8 + 2*tg]   = p23;
        }
        __syncwarp();

        // ---- O += P' @ V(perm) ----
        float pa[4][8];
        {
            const float* Pr0 = &Ps[r0*P68];
            const float* Pr1 = &Ps[(r0+8)*P68];
            *(float4*)&pa[0][0] = *(const float4*)&Pr0[tg*8];
            *(float4*)&pa[0][4] = *(const float4*)&Pr0[tg*8 + 4];
            *(float4*)&pa[1][0] = *(const float4*)&Pr1[tg*8];
            *(float4*)&pa[1][4] = *(const float4*)&Pr1[tg*8 + 4];
            *(float4*)&pa[2][0] = *(const float4*)&Pr0[(tg+4)*8];
            *(float4*)&pa[2][4] = *(const float4*)&Pr0[(tg+4)*8 + 4];
            *(float4*)&pa[3][0] = *(const float4*)&Pr1[(tg+4)*8];
            *(float4*)&pa[3][4] = *(const float4*)&Pr1[(tg+4)*8 + 4];
        }
        #pragma unroll
        for (int ks = 0; ks < 8; ks++) {
            float b0[8], b1[8];
            const float* Vr0 = &Vsp[(ks*8 + tg)*64];
            const float* Vr1 = &Vsp[(ks*8 + tg + 4)*64];
            *(float4*)&b0[0] = *(const float4*)&Vr0[pk0];
            *(float4*)&b0[4] = *(const float4*)&Vr0[pk1];
            *(float4*)&b1[0] = *(const float4*)&Vr1[pk0];
            *(float4*)&b1[4] = *(const float4*)&Vr1[pk1];
            unsigned a[4] = { __float_as_uint(pa[0][ks]), __float_as_uint(pa[1][ks]),
                              __float_as_uint(pa[2][ks]), __float_as_uint(pa[3][ks]) };
            #pragma unroll
            for (int nt = 0; nt < 8; nt++) {
                unsigned bf[2] = { __float_as_uint(b0[nt]), __float_as_uint(b1[nt]) };
                mma_tf32(o[nt], a, bf);
            }
        }

        __syncthreads();
        if (t + 2 < NTILE) {
            load_tile((t+2)*64, t & 1);
            CP_COMMIT();
        }
    }

    // ---- normalize + write O: plain [B,S,H*DH] fp32 ----
    float inv0 = 1.0f / l0, inv1 = 1.0f / l1;
    size_t ob0 = ((size_t)(b*Ssz + q0 + r0)) * Dsz + h*DHs;
    size_t ob1 = ((size_t)(b*Ssz + q0 + r0 + 8)) * Dsz + h*DHs;
    #pragma unroll
    for (int nt = 0; nt < 8; nt++) {
        int n = nt*8 + 2*tg;
        float2 va = make_float2(o[nt][0]*inv0, o[nt][1]*inv0);
        float2 vb = make_float2(o[nt][2]*inv1, o[nt][3]*inv1);
        *(float2*)&O[ob0 + n] = va;
        *(float2*)&O[ob1 + n] = vb;
    }
}

// ---------------------------------------------------------------------------

extern "C" void kernel_launch(void* const* d_in, const int* in_sizes, int n_in,
                              void* d_out, int out_size)
{
    (void)in_sizes; (void)n_in; (void)out_size;
    const float* queries = (const float*)d_in[0];
    const float* keys    = (const float*)d_in[1];
    const float* values  = (const float*)d_in[2];
    const float* Wq = (const float*)d_in[3];
    const float* bq = (const float*)d_in[4];
    const float* Wk = (const float*)d_in[5];
    const float* bk = (const float*)d_in[6];
    const float* Wv = (const float*)d_in[7];
    const float* bv = (const float*)d_in[8];
    const float* Wo = (const float*)d_in[9];
    const float* bo = (const float*)d_in[10];
    float* out = (float*)d_out;

    void *pwq,*pwk,*pwv,*pwo,*pq,*pk,*pv,*po;
    cudaGetSymbolAddress(&pwq, g_wq); cudaGetSymbolAddress(&pwk, g_wk);
    cudaGetSymbolAddress(&pwv, g_wv); cudaGetSymbolAddress(&pwo, g_wo);
    cudaGetSymbolAddress(&pq, g_q);   cudaGetSymbolAddress(&pk, g_k);
    cudaGetSymbolAddress(&pv, g_v);   cudaGetSymbolAddress(&po, g_o);

    cudaFuncSetAttribute(gemm_tf32<0>, cudaFuncAttributeMaxDynamicSharedMemorySize, GEMM_SMEM);
    cudaFuncSetAttribute(gemm_tf32<1>, cudaFuncAttributeMaxDynamicSharedMemorySize, GEMM_SMEM);
    cudaFuncSetAttribute(gemm_tf32<2>, cudaFuncAttributeMaxDynamicSharedMemorySize, GEMM_SMEM);
    cudaFuncSetAttribute(gemm_tf32<3>, cudaFuncAttributeMaxDynamicSharedMemorySize, GEMM_SMEM);
    cudaFuncSetAttribute(attn_mma,     cudaFuncAttributeMaxDynamicSharedMemorySize, ATTN_SMEM);

    // weight converts (tf32 + pi64 cols)
    cvt_w<<<Dsz*Dsz/1024, 256>>>(Wq, (float*)pwq);
    cvt_w<<<Dsz*Dsz/1024, 256>>>(Wk, (float*)pwk);
    cvt_w<<<Dsz*Dsz/1024, 256>>>(Wv, (float*)pwv);
    cvt_w<<<Dsz*Dsz/1024, 256>>>(Wo, (float*)pwo);

    dim3 ggrid(Dsz/128, Mrows/128);   // (8, 32)
    const float qscale = 0.125f * 1.4426950408889634f;   // log2e / sqrt(64)

    gemm_tf32<1><<<ggrid, 256, GEMM_SMEM>>>(queries, (const float*)pwq, bq, (float*)pq, qscale);
    gemm_tf32<3><<<ggrid, 256, GEMM_SMEM>>>(keys,    (const float*)pwk, bk, (float*)pk, 1.0f);
    gemm_tf32<2><<<ggrid, 256, GEMM_SMEM>>>(values,  (const float*)pwv, bv, (float*)pv, 1.0f);

    dim3 agrid(Ssz/128, Hn, Bsz);     // (16, 16, 2)
    attn_mma<<<agrid, 256, ATTN_SMEM>>>((const float*)pq, (const float*)pk,
                                        (const float*)pv, (float*)po);

    gemm_tf32<0><<<ggrid, 256, GEMM_SMEM>>>((const float*)po, (const float*)pwo, bo, out, 1.0f);
}